// round 17
// baseline (speedup 1.0000x reference)
#include <cuda_runtime.h>
#include <cuda_fp16.h>

// Problem constants
#define S_TOTAL    37448       // sum of LAYER_SIZES
#define OUT_TOKENS 5704        // 8 + 64 + 512 + 1024 + 4096
#define BATCH      8
#define TROWS      384         // unified rows: 256 combo + 64 pos1 + 64 pos2
#define PR_ROWS    4           // rows per projection block (96 chunks)

// Scratch (static device globals; no runtime allocation)
__device__ float  g_Wt3[4 * 256 * 256];        // [kk][e][o]
__device__ float  g_Wt4[8 * 256 * 256];
__device__ __half g_tab3[4 * TROWS * 256];     // [kk][row][o] unified fp16 tables
__device__ __half g_tab4[8 * TROWS * 256];

__device__ __forceinline__ __half2 u2h2(unsigned u) {
    return *reinterpret_cast<const __half2*>(&u);
}

// ---------------------------------------------------------------------------
// Kernel 1: fused tiled transpose for BOTH conv weights. (R12, proven)
// ---------------------------------------------------------------------------
__global__ void __launch_bounds__(256) transpose_w_all(
    const float* __restrict__ W3, const float* __restrict__ W4)
{
    __shared__ float sm[8448];

    if (blockIdx.x < 32) {
        constexpr int TO = 64, TE = 32, PAD = 65;
        int bid = blockIdx.x;
        int o0 = (bid % 4) * TO;
        int e0 = (bid / 4) * TE;
        const float4* Wv = reinterpret_cast<const float4*>(W3);

        for (int i = threadIdx.x; i < TO * TE; i += 256) {
            int o_l = i / TE, e_l = i % TE;
            float4 v = Wv[(o0 + o_l) * 256 + (e0 + e_l)];
            sm[(0 * TE + e_l) * PAD + o_l] = v.x;
            sm[(1 * TE + e_l) * PAD + o_l] = v.y;
            sm[(2 * TE + e_l) * PAD + o_l] = v.z;
            sm[(3 * TE + e_l) * PAD + o_l] = v.w;
        }
        __syncthreads();
        for (int i = threadIdx.x; i < 4 * TE * TO; i += 256) {
            int kk = i / (TE * TO);
            int rem = i % (TE * TO);
            int e_l = rem / TO, o_l = rem % TO;
            g_Wt3[kk * 65536 + (e0 + e_l) * 256 + (o0 + o_l)] =
                sm[(kk * TE + e_l) * PAD + o_l];
        }
    } else {
        constexpr int TO = 32, TE = 32, PAD = 33;
        int bid = blockIdx.x - 32;
        int o0 = (bid % 8) * TO;
        int e0 = (bid / 8) * TE;
        const float4* Wv = reinterpret_cast<const float4*>(W4);

        for (int i = threadIdx.x; i < TO * TE; i += 256) {
            int o_l = i / TE, e_l = i % TE;
            int idx = (o0 + o_l) * 256 + (e0 + e_l);
#pragma unroll
            for (int q = 0; q < 2; q++) {
                float4 v = Wv[idx * 2 + q];
                sm[((q * 4 + 0) * TE + e_l) * PAD + o_l] = v.x;
                sm[((q * 4 + 1) * TE + e_l) * PAD + o_l] = v.y;
                sm[((q * 4 + 2) * TE + e_l) * PAD + o_l] = v.z;
                sm[((q * 4 + 3) * TE + e_l) * PAD + o_l] = v.w;
            }
        }
        __syncthreads();
        for (int i = threadIdx.x; i < 8 * TE * TO; i += 256) {
            int kk = i / (TE * TO);
            int rem = i % (TE * TO);
            int e_l = rem / TO, o_l = rem % TO;
            g_Wt4[kk * 65536 + (e0 + e_l) * 256 + (o0 + o_l)] =
                sm[(kk * TE + e_l) * PAD + o_l];
        }
    }
}

// ---------------------------------------------------------------------------
// Kernel 2: unified projection — 384 rows per kk-slice, fp16 output.
// Row rr < 256:      (val_emb[rr>>6] + pos0[rr&63]) . W_kk   (combo, one round)
// 256 <= rr < 320:    pos1[rr-256] . W_kk
// 320 <= rr < 384:    pos2[rr-320] . W_kk
// grid = (96 chunks, 12 slices); block 256 = 64 o-quads x 4 e-quarters.
// PR_ROWS=4 keeps the proven R12 register profile.
// ---------------------------------------------------------------------------
__global__ void __launch_bounds__(256) project_unified_kernel(
    const float* __restrict__ val3, const float* __restrict__ pos3,
    const float* __restrict__ val4, const float* __restrict__ pos4)
{
    int s  = blockIdx.y;            // slice 0..11 (0-3 -> layer3, 4-11 -> layer4)
    int r0 = blockIdx.x * PR_ROWS;

    const float* Wt; __half* tab; const float* ve; const float* pe;
    if (s < 4) { Wt = g_Wt3 + s * 65536;        tab = g_tab3 + s * (TROWS * 256);
                 ve = val3; pe = pos3; }
    else       { int kk = s - 4;
                 Wt = g_Wt4 + kk * 65536;       tab = g_tab4 + kk * (TROWS * 256);
                 ve = val4; pe = pos4; }

    int o4 = threadIdx.x & 63;
    int eh = threadIdx.x >> 6;
    int ebase = eh * 64;

    __shared__ float  srow[PR_ROWS][256];
    __shared__ float4 sred[3][PR_ROWS][64];

    for (int i = threadIdx.x; i < PR_ROWS * 256; i += 256) {
        int r = i >> 8, c = i & 255;
        int rr = r0 + r;
        float x;
        if (rr < 256) {
            x = ve[(rr >> 6) * 256 + c] + pe[(rr & 63) * 256 + c];
        } else if (rr < 320) {
            x = pe[(64 + (rr - 256)) * 256 + c];
        } else {
            x = pe[(128 + (rr - 320)) * 256 + c];
        }
        srow[r][c] = x;
    }
    __syncthreads();

    float4 acc[PR_ROWS];
#pragma unroll
    for (int r = 0; r < PR_ROWS; r++) acc[r] = make_float4(0.f, 0.f, 0.f, 0.f);

    const float4* Wv = reinterpret_cast<const float4*>(Wt);
#pragma unroll 8
    for (int e = 0; e < 64; e++) {
        float4 w = Wv[(ebase + e) * 64 + o4];
#pragma unroll
        for (int r = 0; r < PR_ROWS; r++) {
            float x = srow[r][ebase + e];
            acc[r].x += x * w.x; acc[r].y += x * w.y;
            acc[r].z += x * w.z; acc[r].w += x * w.w;
        }
    }

    if (eh > 0) {
#pragma unroll
        for (int r = 0; r < PR_ROWS; r++) sred[eh - 1][r][o4] = acc[r];
    }
    __syncthreads();
    if (eh == 0) {
#pragma unroll
        for (int r = 0; r < PR_ROWS; r++) {
            float4 a = acc[r];
            float4 b0 = sred[0][r][o4], b1 = sred[1][r][o4], b2 = sred[2][r][o4];
            a.x += b0.x + b1.x + b2.x;
            a.y += b0.y + b1.y + b2.y;
            a.z += b0.z + b1.z + b2.z;
            a.w += b0.w + b1.w + b2.w;
            __half2* dst = reinterpret_cast<__half2*>(tab + (r0 + r) * 256 + o4 * 4);
            dst[0] = __floats2half2_rn(a.x, a.y);
            dst[1] = __floats2half2_rn(a.z, a.w);
        }
    }
}

// ---------------------------------------------------------------------------
// Layers 0-2 (pure embedding sum), fp32 exact. (proven)
// ---------------------------------------------------------------------------
__global__ void __launch_bounds__(256) embed_small_kernel(
    const int* __restrict__ value,
    const int* __restrict__ depth,
    const int* __restrict__ position,
    const float* __restrict__ v0, const float* __restrict__ v1, const float* __restrict__ v2,
    const float* __restrict__ p0, const float* __restrict__ p1, const float* __restrict__ p2,
    const float* __restrict__ d0, const float* __restrict__ d1, const float* __restrict__ d2,
    float* __restrict__ out)
{
    int idx = blockIdx.x * blockDim.x + threadIdx.x;
    int lane  = idx & 63;
    int token = idx >> 6;
    if (token >= BATCH * 584) return;
    int b = token / 584;
    int s = token % 584;

    const float *ve, *pe, *de;
    if (s < 8)       { ve = v0; pe = p0; de = d0; }
    else if (s < 72) { ve = v1; pe = p1; de = d1; }
    else             { ve = v2; pe = p2; de = d2; }

    int base = b * S_TOTAL + s;
    int v = value[base];
    int d = depth[base];
    const int* pp = position + base * 3;
    int q0 = pp[0], q1 = pp[1], q2 = pp[2];

    const float4* V  = reinterpret_cast<const float4*>(ve) + v * 64 + lane;
    const float4* P0 = reinterpret_cast<const float4*>(pe) + (q0)       * 64 + lane;
    const float4* P1 = reinterpret_cast<const float4*>(pe) + (64 + q1)  * 64 + lane;
    const float4* P2 = reinterpret_cast<const float4*>(pe) + (128 + q2) * 64 + lane;
    const float4* D  = reinterpret_cast<const float4*>(de) + d * 64 + lane;

    float4 a = *V, x;
    x = *P0; a.x += x.x; a.y += x.y; a.z += x.z; a.w += x.w;
    x = *P1; a.x += x.x; a.y += x.y; a.z += x.z; a.w += x.w;
    x = *P2; a.x += x.x; a.y += x.y; a.z += x.z; a.w += x.w;
    x = *D;  a.x += x.x; a.y += x.y; a.z += x.z; a.w += x.w;

    reinterpret_cast<float4*>(out)[(b * OUT_TOKENS + s) * 64 + lane] = a;
}

// ---------------------------------------------------------------------------
// conv via unified table — 3 gathers per kk (R10-verified math, R9 body).
// warp = one token; lane-parallel index fetch, prefused, shfl-broadcast.
// ---------------------------------------------------------------------------
template <int K>
__global__ void __launch_bounds__(256) conv_tri_kernel(
    const int* __restrict__ value,
    const int* __restrict__ position,
    const float* __restrict__ bias,
    float* __restrict__ out,
    int in_start, int out_row_start, int t_per_b)
{
    const __half* tab = (K == 4) ? g_tab3 : g_tab4;

    int gwarp = (blockIdx.x * blockDim.x + threadIdx.x) >> 5;
    int lane  = threadIdx.x & 31;
    if (gwarp >= BATCH * t_per_b) return;
    int b = gwarp / t_per_b;
    int t = gwarp % t_per_b;

    int sbase = b * S_TOTAL + in_start + t * K;

    int vload = (lane < K)     ? value[sbase + lane]        : 0;
    int pload = (lane < 3 * K) ? position[sbase * 3 + lane] : 0;

    int q0l = __shfl_sync(0xffffffffu, pload, (lane * 3)     & 31);
    int q1l = __shfl_sync(0xffffffffu, pload, (lane * 3 + 1) & 31);
    int q2l = __shfl_sync(0xffffffffu, pload, (lane * 3 + 2) & 31);
    int iA = vload * 64 + q0l;       // combo row [0,256)
    int i1 = 256 + q1l;
    int i2 = 320 + q2l;

    float acc[8];
    {
        const float4* bv = reinterpret_cast<const float4*>(bias);
        float4 b0 = bv[lane * 2], b1 = bv[lane * 2 + 1];
        acc[0] = b0.x; acc[1] = b0.y; acc[2] = b0.z; acc[3] = b0.w;
        acc[4] = b1.x; acc[5] = b1.y; acc[6] = b1.z; acc[7] = b1.w;
    }

#pragma unroll
    for (int kk = 0; kk < K; kk++) {
        int rA = __shfl_sync(0xffffffffu, iA, kk);
        int r1 = __shfl_sync(0xffffffffu, i1, kk);
        int r2 = __shfl_sync(0xffffffffu, i2, kk);

        const uint4* P = reinterpret_cast<const uint4*>(tab + kk * (TROWS * 256));
        uint4 ua = P[rA * 32 + lane];
        uint4 u1 = P[r1 * 32 + lane];
        uint4 u2 = P[r2 * 32 + lane];

        __half2 sx = __hadd2(__hadd2(u2h2(ua.x), u2h2(u1.x)), u2h2(u2.x));
        __half2 sy = __hadd2(__hadd2(u2h2(ua.y), u2h2(u1.y)), u2h2(u2.y));
        __half2 sz = __hadd2(__hadd2(u2h2(ua.z), u2h2(u1.z)), u2h2(u2.z));
        __half2 sw = __hadd2(__hadd2(u2h2(ua.w), u2h2(u1.w)), u2h2(u2.w));

        float2 f;
        f = __half22float2(sx); acc[0] += f.x; acc[1] += f.y;
        f = __half22float2(sy); acc[2] += f.x; acc[3] += f.y;
        f = __half22float2(sz); acc[4] += f.x; acc[5] += f.y;
        f = __half22float2(sw); acc[6] += f.x; acc[7] += f.y;
    }

    int row = b * OUT_TOKENS + out_row_start + t;
    float4* dst = reinterpret_cast<float4*>(out + row * 256 + lane * 8);
    dst[0] = make_float4(acc[0], acc[1], acc[2], acc[3]);
    dst[1] = make_float4(acc[4], acc[5], acc[6], acc[7]);
}

// ---------------------------------------------------------------------------
// Launch. Inputs classified BY ELEMENT COUNT.
// Critical path (s0): transpose -> projectU -> conv4.   (no buildA node)
// Side (s1): embed at t=0; conv3 after projectU (hidden under conv4).
// Submission: transpose(#1), projectU(#2), embed(#3), conv4(#4 = ncu slot),
// conv3(#5).
// ---------------------------------------------------------------------------
extern "C" void kernel_launch(void* const* d_in, const int* in_sizes, int n_in,
                              void* d_out, int out_size) {
    const int* value = nullptr;
    const int* depth = nullptr;
    const int* position = nullptr;
    const float* val_emb[5] = {};
    const float* pos_emb[5] = {};
    const float* dep_emb[3] = {};
    const float* conv_w3 = nullptr;
    const float* conv_w4 = nullptr;
    const float* conv_b3 = nullptr;
    const float* conv_b4 = nullptr;

    int n_val = 0, n_pos = 0, n_dep = 0, n_cb = 0, n_vd = 0;
    for (int i = 0; i < n_in; i++) {
        int sz = in_sizes[i];
        const void* p = d_in[i];
        switch (sz) {
            case 299584:
                if (n_vd++ == 0) value = (const int*)p; else depth = (const int*)p;
                break;
            case 898752:  position = (const int*)p; break;
            case 1024:    if (n_val < 5) val_emb[n_val++] = (const float*)p; break;
            case 49152:   if (n_pos < 5) pos_emb[n_pos++] = (const float*)p; break;
            case 1536:    if (n_dep < 3) dep_emb[n_dep++] = (const float*)p; break;
            case 262144:  conv_w3 = (const float*)p; break;
            case 524288:  conv_w4 = (const float*)p; break;
            case 256:
                if (n_cb++ == 0) conv_b3 = (const float*)p; else conv_b4 = (const float*)p;
                break;
            default: break;
        }
    }

    float* out = (float*)d_out;

    // Lazily-created side stream + events (host objects only).
    static cudaStream_t s1 = nullptr;
    static cudaEvent_t evStart = nullptr, evProj = nullptr, evSide = nullptr;
    if (!s1) {
        cudaStreamCreateWithFlags(&s1, cudaStreamNonBlocking);
        cudaEventCreateWithFlags(&evStart, cudaEventDisableTiming);
        cudaEventCreateWithFlags(&evProj,  cudaEventDisableTiming);
        cudaEventCreateWithFlags(&evSide,  cudaEventDisableTiming);
    }

    // Fork point.
    cudaEventRecord(evStart, 0);

    // ---- s0 (main/capture stream): critical path ----
    transpose_w_all<<<96, 256>>>(conv_w3, conv_w4);                         // #1
    project_unified_kernel<<<dim3(TROWS / PR_ROWS, 12), 256>>>(             // #2
        val_emb[3], pos_emb[3], val_emb[4], pos_emb[4]);
    cudaEventRecord(evProj, 0);

    // ---- s1: embed at t=0 (independent of precompute) ----
    cudaStreamWaitEvent(s1, evStart, 0);
    {   // #3: embed layers 0-2
        int threads = BATCH * 584 * 64;
        embed_small_kernel<<<(threads + 255) / 256, 256, 0, s1>>>(
            value, depth, position,
            val_emb[0], val_emb[1], val_emb[2],
            pos_emb[0], pos_emb[1], pos_emb[2],
            dep_emb[0], dep_emb[1], dep_emb[2],
            out);
    }

    {   // #4 (ncu capture slot): conv4 on main stream
        int warps4 = BATCH * 4096;
        conv_tri_kernel<8><<<(warps4 * 32 + 255) / 256, 256>>>(
            value, position, conv_b4, out,
            /*in_start=*/4680, /*out_row_start=*/1608, /*t_per_b=*/4096);
    }

    // ---- s1 tail: conv3 after projectU, concurrent with conv4 ----
    cudaStreamWaitEvent(s1, evProj, 0);
    {   // #5: conv3
        int warps3 = BATCH * 1024;
        conv_tri_kernel<4><<<(warps3 * 32 + 255) / 256, 256, 0, s1>>>(
            value, position, conv_b3, out,
            /*in_start=*/584, /*out_row_start=*/584, /*t_per_b=*/1024);
    }
    cudaEventRecord(evSide, s1);

    // Join.
    cudaStreamWaitEvent(0, evSide, 0);
}